// round 4
// baseline (speedup 1.0000x reference)
#include <cuda_runtime.h>
#include <utility>
#include <cstddef>

// ============================================================================
// SO(3) tensor product: out[n,c,k] = sum_{i,j} cg[i,j,k] * x[n,c,i] * y[n,c,j]
// CG (Wigner-3j) coefficients are evaluated at COMPILE TIME via constexpr and
// template expansion, so every coefficient becomes an FFMA immediate.
// Memory-bound on output stores (~1 GB); staged through smem for perfectly
// coalesced float4 writes.
// ============================================================================

namespace tp {

struct CGE { int i; int j; int k; float v; };

__host__ __device__ constexpr double cfact(int n) {
    double r = 1.0;
    for (int i = 2; i <= n; ++i) r *= (double)i;
    return r;
}

__host__ __device__ constexpr double csqrt(double x) {
    if (x <= 0.0) return 0.0;
    double g = x < 1.0 ? 1.0 : x;
    for (int it = 0; it < 48; ++it) g = 0.5 * (g + x / g);
    return g;
}

__host__ __device__ constexpr double w3j(int j1, int j2, int j3,
                                         int m1, int m2, int m3) {
    if (m1 + m2 + m3 != 0) return 0.0;
    int dlo = j1 > j2 ? j1 - j2 : j2 - j1;
    if (j3 < dlo || j3 > j1 + j2) return 0.0;
    int t1 = j2 - m1 - j3;
    int t2 = j1 + m2 - j3;
    int t3 = j1 + j2 - j3;
    int t4 = j1 - m1;
    int t5 = j2 + m2;
    int tmin = 0; if (t1 > tmin) tmin = t1; if (t2 > tmin) tmin = t2;
    int tmax = t3; if (t4 < tmax) tmax = t4; if (t5 < tmax) tmax = t5;
    if (tmin > tmax) return 0.0;
    double s = 0.0;
    for (int t = tmin; t <= tmax; ++t) {
        double term = 1.0 / (cfact(t) * cfact(t - t1) * cfact(t - t2)
                             * cfact(t3 - t) * cfact(t4 - t) * cfact(t5 - t));
        if (t & 1) term = -term;
        s += term;
    }
    double pref = csqrt(
        cfact(j1 + j2 - j3) * cfact(j1 - j2 + j3) * cfact(-j1 + j2 + j3)
        / cfact(j1 + j2 + j3 + 1)
        * cfact(j1 + m1) * cfact(j1 - m1)
        * cfact(j2 + m2) * cfact(j2 - m2)
        * cfact(j3 + m3) * cfact(j3 - m3));
    int ex = j1 - j2 - m3;
    if (ex % 2 != 0) pref = -pref;
    return pref * s;
}

// Entries are enumerated in globally ascending output-index (k) order:
// blocks in reference order (l1, l2, l3), k = block_offset + m3 + l3 ascending.
__host__ __device__ constexpr int cg_count_below(int K) {
    int n = 0;
    int off = 0;
    for (int l1 = 0; l1 <= 3; ++l1)
    for (int l2 = 0; l2 <= 3; ++l2) {
        int lo = l1 > l2 ? l1 - l2 : l2 - l1;
        int hi = (l1 + l2) < 3 ? (l1 + l2) : 3;
        for (int l3 = lo; l3 <= hi; ++l3) {
            for (int m3 = -l3; m3 <= l3; ++m3) {
                int k = off + m3 + l3;
                if (k < K) {
                    for (int m1 = -l1; m1 <= l1; ++m1) {
                        int m2 = -m1 - m3;
                        if (m2 < -l2 || m2 > l2) continue;
                        double w = w3j(l1, l2, l3, m1, m2, m3);
                        if (w > 1e-12 || w < -1e-12) ++n;
                    }
                }
            }
            off += 2 * l3 + 1;
        }
    }
    return n;
}

__host__ __device__ constexpr CGE cg_entry(int idx) {
    int n = 0;
    int off = 0;
    for (int l1 = 0; l1 <= 3; ++l1)
    for (int l2 = 0; l2 <= 3; ++l2) {
        int lo = l1 > l2 ? l1 - l2 : l2 - l1;
        int hi = (l1 + l2) < 3 ? (l1 + l2) : 3;
        for (int l3 = lo; l3 <= hi; ++l3) {
            for (int m3 = -l3; m3 <= l3; ++m3) {
                int k = off + m3 + l3;
                for (int m1 = -l1; m1 <= l1; ++m1) {
                    int m2 = -m1 - m3;
                    if (m2 < -l2 || m2 > l2) continue;
                    double w = w3j(l1, l2, l3, m1, m2, m3);
                    if (w > 1e-12 || w < -1e-12) {
                        if (n == idx) return CGE{m1 + l1, m2 + l2, k, (float)w};
                        ++n;
                    }
                }
            }
            off += 2 * l3 + 1;
        }
    }
    return CGE{0, 0, 0, 0.0f};
}

constexpr int DIM_OUT = 156;
constexpr int TPB = 128;
constexpr int STR4 = 9;   // smem row stride: 9 float4 = 36 floats (conflict-free)

template <int E, int K0>
__device__ __forceinline__ void term(const float* xr, const float* yr, float* acc) {
    constexpr CGE e = cg_entry(E);   // compile-time: immediate coefficient
    acc[e.k - K0] = fmaf(e.v, xr[e.i] * yr[e.j], acc[e.k - K0]);
}

template <int K0, int E0, size_t... Is>
__device__ __forceinline__ void terms(std::index_sequence<Is...>,
                                      const float* xr, const float* yr, float* acc) {
    (term<E0 + (int)Is, K0>(xr, yr, acc), ...);
}

// One k-pass: accumulate KPP output components in registers, stage the block's
// [128 x KPP] tile in smem, then stream it out as fully coalesced float4s.
template <int K0, int KPP>
__device__ __forceinline__ void do_pass(const float* xr, const float* yr,
                                        float4* tile4, float4* __restrict__ out4,
                                        size_t base4, int tid, int validPairs) {
    float acc[KPP] = {};
    constexpr int E0 = cg_count_below(K0);
    constexpr int E1 = cg_count_below(K0 + KPP);
    terms<K0, E0>(std::make_index_sequence<(size_t)(E1 - E0)>{}, xr, yr, acc);

    constexpr int V = KPP / 4;   // float4s per pair in this pass
    #pragma unroll
    for (int q = 0; q < V; ++q)
        tile4[tid * STR4 + q] =
            make_float4(acc[4 * q + 0], acc[4 * q + 1], acc[4 * q + 2], acc[4 * q + 3]);
    __syncthreads();

    int tot4 = validPairs * V;
    #pragma unroll 1
    for (int g4 = tid; g4 < tot4; g4 += TPB) {
        int p = g4 / V;          // V is a compile-time constant (8 or 7)
        int q = g4 - p * V;
        float4 v = tile4[p * STR4 + q];
        out4[base4 + (size_t)p * (DIM_OUT / 4) + (K0 / 4) + q] = v;
    }
    __syncthreads();
}

__global__ void __launch_bounds__(TPB)
tp_kernel(const float* __restrict__ x, const float* __restrict__ y,
          float* __restrict__ out, int npairs) {
    __shared__ float4 tile4[TPB * STR4];   // 18432 bytes
    int tid = threadIdx.x;
    int pair = blockIdx.x * TPB + tid;

    float xr[7], yr[7];
    if (pair < npairs) {
        const float* xp = x + (size_t)pair * 7;
        const float* yp = y + (size_t)pair * 7;
        #pragma unroll
        for (int i = 0; i < 7; ++i) { xr[i] = __ldg(xp + i); yr[i] = __ldg(yp + i); }
    } else {
        #pragma unroll
        for (int i = 0; i < 7; ++i) { xr[i] = 0.0f; yr[i] = 0.0f; }
    }

    int validPairs = npairs - blockIdx.x * TPB;
    if (validPairs > TPB) validPairs = TPB;

    float4* out4 = reinterpret_cast<float4*>(out);
    size_t base4 = (size_t)blockIdx.x * (TPB * (DIM_OUT / 4));

    do_pass<0,   32>(xr, yr, tile4, out4, base4, tid, validPairs);
    do_pass<32,  32>(xr, yr, tile4, out4, base4, tid, validPairs);
    do_pass<64,  32>(xr, yr, tile4, out4, base4, tid, validPairs);
    do_pass<96,  32>(xr, yr, tile4, out4, base4, tid, validPairs);
    do_pass<128, 28>(xr, yr, tile4, out4, base4, tid, validPairs);
}

}  // namespace tp

extern "C" void kernel_launch(void* const* d_in, const int* in_sizes, int n_in,
                              void* d_out, int out_size) {
    (void)n_in; (void)out_size;
    const float* x = (const float*)d_in[0];
    const float* y = (const float*)d_in[1];
    float* out = (float*)d_out;
    int npairs = in_sizes[0] / 7;               // E * C
    int blocks = (npairs + tp::TPB - 1) / tp::TPB;
    tp::tp_kernel<<<blocks, tp::TPB>>>(x, y, out, npairs);
}

// round 7
// speedup vs baseline: 1.0015x; 1.0015x over previous
#include <cuda_runtime.h>
#include <utility>
#include <cstddef>

// ============================================================================
// SO(3) tensor product: out[n,c,k] = sum_{i,j} cg[i,j,k] * x[n,c,i] * y[n,c,j]
// CG (Wigner-3j) coefficients are evaluated at COMPILE TIME via constexpr and
// template expansion, so every coefficient becomes an FFMA immediate.
// Memory-bound on output stores (~1 GB); staged through smem for perfectly
// coalesced float4 writes.
// ============================================================================

namespace tp {

struct CGE { int i; int j; int k; float v; };

__host__ __device__ constexpr double cfact(int n) {
    double r = 1.0;
    for (int i = 2; i <= n; ++i) r *= (double)i;
    return r;
}

__host__ __device__ constexpr double csqrt(double x) {
    if (x <= 0.0) return 0.0;
    double g = x < 1.0 ? 1.0 : x;
    for (int it = 0; it < 48; ++it) g = 0.5 * (g + x / g);
    return g;
}

__host__ __device__ constexpr double w3j(int j1, int j2, int j3,
                                         int m1, int m2, int m3) {
    if (m1 + m2 + m3 != 0) return 0.0;
    int dlo = j1 > j2 ? j1 - j2 : j2 - j1;
    if (j3 < dlo || j3 > j1 + j2) return 0.0;
    int t1 = j2 - m1 - j3;
    int t2 = j1 + m2 - j3;
    int t3 = j1 + j2 - j3;
    int t4 = j1 - m1;
    int t5 = j2 + m2;
    int tmin = 0; if (t1 > tmin) tmin = t1; if (t2 > tmin) tmin = t2;
    int tmax = t3; if (t4 < tmax) tmax = t4; if (t5 < tmax) tmax = t5;
    if (tmin > tmax) return 0.0;
    double s = 0.0;
    for (int t = tmin; t <= tmax; ++t) {
        double term = 1.0 / (cfact(t) * cfact(t - t1) * cfact(t - t2)
                             * cfact(t3 - t) * cfact(t4 - t) * cfact(t5 - t));
        if (t & 1) term = -term;
        s += term;
    }
    double pref = csqrt(
        cfact(j1 + j2 - j3) * cfact(j1 - j2 + j3) * cfact(-j1 + j2 + j3)
        / cfact(j1 + j2 + j3 + 1)
        * cfact(j1 + m1) * cfact(j1 - m1)
        * cfact(j2 + m2) * cfact(j2 - m2)
        * cfact(j3 + m3) * cfact(j3 - m3));
    int ex = j1 - j2 - m3;
    if (ex % 2 != 0) pref = -pref;
    return pref * s;
}

// Entries are enumerated in globally ascending output-index (k) order:
// blocks in reference order (l1, l2, l3), k = block_offset + m3 + l3 ascending.
__host__ __device__ constexpr int cg_count_below(int K) {
    int n = 0;
    int off = 0;
    for (int l1 = 0; l1 <= 3; ++l1)
    for (int l2 = 0; l2 <= 3; ++l2) {
        int lo = l1 > l2 ? l1 - l2 : l2 - l1;
        int hi = (l1 + l2) < 3 ? (l1 + l2) : 3;
        for (int l3 = lo; l3 <= hi; ++l3) {
            for (int m3 = -l3; m3 <= l3; ++m3) {
                int k = off + m3 + l3;
                if (k < K) {
                    for (int m1 = -l1; m1 <= l1; ++m1) {
                        int m2 = -m1 - m3;
                        if (m2 < -l2 || m2 > l2) continue;
                        double w = w3j(l1, l2, l3, m1, m2, m3);
                        if (w > 1e-12 || w < -1e-12) ++n;
                    }
                }
            }
            off += 2 * l3 + 1;
        }
    }
    return n;
}

__host__ __device__ constexpr CGE cg_entry(int idx) {
    int n = 0;
    int off = 0;
    for (int l1 = 0; l1 <= 3; ++l1)
    for (int l2 = 0; l2 <= 3; ++l2) {
        int lo = l1 > l2 ? l1 - l2 : l2 - l1;
        int hi = (l1 + l2) < 3 ? (l1 + l2) : 3;
        for (int l3 = lo; l3 <= hi; ++l3) {
            for (int m3 = -l3; m3 <= l3; ++m3) {
                int k = off + m3 + l3;
                for (int m1 = -l1; m1 <= l1; ++m1) {
                    int m2 = -m1 - m3;
                    if (m2 < -l2 || m2 > l2) continue;
                    double w = w3j(l1, l2, l3, m1, m2, m3);
                    if (w > 1e-12 || w < -1e-12) {
                        if (n == idx) return CGE{m1 + l1, m2 + l2, k, (float)w};
                        ++n;
                    }
                }
            }
            off += 2 * l3 + 1;
        }
    }
    return CGE{0, 0, 0, 0.0f};
}

constexpr int DIM_OUT = 156;
constexpr int TPB = 128;
constexpr int STR4 = 9;   // smem row stride: 9 float4 = 36 floats (conflict-free)

template <int E, int K0>
__device__ __forceinline__ void term(const float* xr, const float* yr, float* acc) {
    constexpr CGE e = cg_entry(E);   // compile-time: immediate coefficient
    acc[e.k - K0] = fmaf(e.v, xr[e.i] * yr[e.j], acc[e.k - K0]);
}

template <int K0, int E0, size_t... Is>
__device__ __forceinline__ void terms(std::index_sequence<Is...>,
                                      const float* xr, const float* yr, float* acc) {
    (term<E0 + (int)Is, K0>(xr, yr, acc), ...);
}

// One k-pass: accumulate KPP output components in registers, stage the block's
// [128 x KPP] tile in smem, then stream it out as fully coalesced float4s.
template <int K0, int KPP>
__device__ __forceinline__ void do_pass(const float* xr, const float* yr,
                                        float4* tile4, float4* __restrict__ out4,
                                        size_t base4, int tid, int validPairs) {
    float acc[KPP] = {};
    constexpr int E0 = cg_count_below(K0);
    constexpr int E1 = cg_count_below(K0 + KPP);
    terms<K0, E0>(std::make_index_sequence<(size_t)(E1 - E0)>{}, xr, yr, acc);

    constexpr int V = KPP / 4;   // float4s per pair in this pass
    #pragma unroll
    for (int q = 0; q < V; ++q)
        tile4[tid * STR4 + q] =
            make_float4(acc[4 * q + 0], acc[4 * q + 1], acc[4 * q + 2], acc[4 * q + 3]);
    __syncthreads();

    int tot4 = validPairs * V;
    #pragma unroll 1
    for (int g4 = tid; g4 < tot4; g4 += TPB) {
        int p = g4 / V;          // V is a compile-time constant (8 or 7)
        int q = g4 - p * V;
        float4 v = tile4[p * STR4 + q];
        out4[base4 + (size_t)p * (DIM_OUT / 4) + (K0 / 4) + q] = v;
    }
    __syncthreads();
}

__global__ void __launch_bounds__(TPB)
tp_kernel(const float* __restrict__ x, const float* __restrict__ y,
          float* __restrict__ out, int npairs) {
    __shared__ float4 tile4[TPB * STR4];   // 18432 bytes
    int tid = threadIdx.x;
    int pair = blockIdx.x * TPB + tid;

    float xr[7], yr[7];
    if (pair < npairs) {
        const float* xp = x + (size_t)pair * 7;
        const float* yp = y + (size_t)pair * 7;
        #pragma unroll
        for (int i = 0; i < 7; ++i) { xr[i] = __ldg(xp + i); yr[i] = __ldg(yp + i); }
    } else {
        #pragma unroll
        for (int i = 0; i < 7; ++i) { xr[i] = 0.0f; yr[i] = 0.0f; }
    }

    int validPairs = npairs - blockIdx.x * TPB;
    if (validPairs > TPB) validPairs = TPB;

    float4* out4 = reinterpret_cast<float4*>(out);
    size_t base4 = (size_t)blockIdx.x * (TPB * (DIM_OUT / 4));

    do_pass<0,   32>(xr, yr, tile4, out4, base4, tid, validPairs);
    do_pass<32,  32>(xr, yr, tile4, out4, base4, tid, validPairs);
    do_pass<64,  32>(xr, yr, tile4, out4, base4, tid, validPairs);
    do_pass<96,  32>(xr, yr, tile4, out4, base4, tid, validPairs);
    do_pass<128, 28>(xr, yr, tile4, out4, base4, tid, validPairs);
}

}  // namespace tp

extern "C" void kernel_launch(void* const* d_in, const int* in_sizes, int n_in,
                              void* d_out, int out_size) {
    (void)n_in; (void)out_size;
    const float* x = (const float*)d_in[0];
    const float* y = (const float*)d_in[1];
    float* out = (float*)d_out;
    int npairs = in_sizes[0] / 7;               // E * C
    int blocks = (npairs + tp::TPB - 1) / tp::TPB;
    tp::tp_kernel<<<blocks, tp::TPB>>>(x, y, out, npairs);
}

// round 10
// speedup vs baseline: 1.2252x; 1.2234x over previous
#include <cuda_runtime.h>
#include <utility>
#include <cstddef>

// ============================================================================
// SO(3) tensor product: out[n,c,k] = sum_{i,j} cg[i,j,k] * x[n,c,i] * y[n,c,j]
// CG coefficients are compile-time constants (FFMA immediates).
// R7: fully-static unrolled drain (exploits npairs % 128 == 0), XOR-swizzled
// 16KB smem tile, cooperative float4 input staging, streaming stores.
// ============================================================================

namespace tp {

struct CGE { int i; int j; int k; float v; };

__host__ __device__ constexpr double cfact(int n) {
    double r = 1.0;
    for (int i = 2; i <= n; ++i) r *= (double)i;
    return r;
}

__host__ __device__ constexpr double csqrt(double x) {
    if (x <= 0.0) return 0.0;
    double g = x < 1.0 ? 1.0 : x;
    for (int it = 0; it < 48; ++it) g = 0.5 * (g + x / g);
    return g;
}

__host__ __device__ constexpr double w3j(int j1, int j2, int j3,
                                         int m1, int m2, int m3) {
    if (m1 + m2 + m3 != 0) return 0.0;
    int dlo = j1 > j2 ? j1 - j2 : j2 - j1;
    if (j3 < dlo || j3 > j1 + j2) return 0.0;
    int t1 = j2 - m1 - j3;
    int t2 = j1 + m2 - j3;
    int t3 = j1 + j2 - j3;
    int t4 = j1 - m1;
    int t5 = j2 + m2;
    int tmin = 0; if (t1 > tmin) tmin = t1; if (t2 > tmin) tmin = t2;
    int tmax = t3; if (t4 < tmax) tmax = t4; if (t5 < tmax) tmax = t5;
    if (tmin > tmax) return 0.0;
    double s = 0.0;
    for (int t = tmin; t <= tmax; ++t) {
        double term = 1.0 / (cfact(t) * cfact(t - t1) * cfact(t - t2)
                             * cfact(t3 - t) * cfact(t4 - t) * cfact(t5 - t));
        if (t & 1) term = -term;
        s += term;
    }
    double pref = csqrt(
        cfact(j1 + j2 - j3) * cfact(j1 - j2 + j3) * cfact(-j1 + j2 + j3)
        / cfact(j1 + j2 + j3 + 1)
        * cfact(j1 + m1) * cfact(j1 - m1)
        * cfact(j2 + m2) * cfact(j2 - m2)
        * cfact(j3 + m3) * cfact(j3 - m3));
    int ex = j1 - j2 - m3;
    if (ex % 2 != 0) pref = -pref;
    return pref * s;
}

__host__ __device__ constexpr int cg_count_below(int K) {
    int n = 0;
    int off = 0;
    for (int l1 = 0; l1 <= 3; ++l1)
    for (int l2 = 0; l2 <= 3; ++l2) {
        int lo = l1 > l2 ? l1 - l2 : l2 - l1;
        int hi = (l1 + l2) < 3 ? (l1 + l2) : 3;
        for (int l3 = lo; l3 <= hi; ++l3) {
            for (int m3 = -l3; m3 <= l3; ++m3) {
                int k = off + m3 + l3;
                if (k < K) {
                    for (int m1 = -l1; m1 <= l1; ++m1) {
                        int m2 = -m1 - m3;
                        if (m2 < -l2 || m2 > l2) continue;
                        double w = w3j(l1, l2, l3, m1, m2, m3);
                        if (w > 1e-12 || w < -1e-12) ++n;
                    }
                }
            }
            off += 2 * l3 + 1;
        }
    }
    return n;
}

__host__ __device__ constexpr CGE cg_entry(int idx) {
    int n = 0;
    int off = 0;
    for (int l1 = 0; l1 <= 3; ++l1)
    for (int l2 = 0; l2 <= 3; ++l2) {
        int lo = l1 > l2 ? l1 - l2 : l2 - l1;
        int hi = (l1 + l2) < 3 ? (l1 + l2) : 3;
        for (int l3 = lo; l3 <= hi; ++l3) {
            for (int m3 = -l3; m3 <= l3; ++m3) {
                int k = off + m3 + l3;
                for (int m1 = -l1; m1 <= l1; ++m1) {
                    int m2 = -m1 - m3;
                    if (m2 < -l2 || m2 > l2) continue;
                    double w = w3j(l1, l2, l3, m1, m2, m3);
                    if (w > 1e-12 || w < -1e-12) {
                        if (n == idx) return CGE{m1 + l1, m2 + l2, k, (float)w};
                        ++n;
                    }
                }
            }
            off += 2 * l3 + 1;
        }
    }
    return CGE{0, 0, 0, 0.0f};
}

constexpr int DIM_OUT  = 156;
constexpr int DIM_OUT4 = DIM_OUT / 4;   // 39
constexpr int TPB = 128;

template <int E, int K0>
__device__ __forceinline__ void term(const float* xr, const float* yr, float* acc) {
    constexpr CGE e = cg_entry(E);   // compile-time: immediate coefficient
    acc[e.k - K0] = fmaf(e.v, xr[e.i] * yr[e.j], acc[e.k - K0]);
}

template <int K0, int E0, size_t... Is>
__device__ __forceinline__ void terms(std::index_sequence<Is...>,
                                      const float* xr, const float* yr, float* acc) {
    (term<E0 + (int)Is, K0>(xr, yr, acc), ...);
}

template <int K0, int KPP>
__device__ __forceinline__ void compute_and_stage(const float* xr, const float* yr,
                                                  float4* buf, int tid) {
    float acc[KPP] = {};
    constexpr int E0 = cg_count_below(K0);
    constexpr int E1 = cg_count_below(K0 + KPP);
    terms<K0, E0>(std::make_index_sequence<(size_t)(E1 - E0)>{}, xr, yr, acc);
    constexpr int V = KPP / 4;
    #pragma unroll
    for (int q = 0; q < V; ++q)                         // XOR swizzle, stride 8
        buf[tid * 8 + (q ^ (tid & 7))] =
            make_float4(acc[4 * q + 0], acc[4 * q + 1], acc[4 * q + 2], acc[4 * q + 3]);
}

// -------- fast path: full block (128 valid pairs), fully static drain --------
template <int K0, int KPP>
__device__ __forceinline__ void pass_fast(const float* xr, const float* yr,
                                          float4* buf, float4* __restrict__ out4,
                                          size_t base4, int tid) {
    compute_and_stage<K0, KPP>(xr, yr, buf, tid);
    __syncthreads();
    constexpr int V = KPP / 4;
    if (V == 8) {
        const int q = tid & 7;
        const int r = tid >> 3;
        #pragma unroll
        for (int u = 0; u < 8; ++u) {                   // 8 independent LDS->STG chains
            int p = r + 16 * u;
            float4 v = buf[p * 8 + (q ^ (p & 7))];
            __stcs(&out4[base4 + (size_t)p * DIM_OUT4 + (K0 / 4) + q], v);
        }
    } else {                                            // V == 7 (last pass)
        #pragma unroll
        for (int u = 0; u < V; ++u) {
            int g4 = tid + TPB * u;
            int p = g4 / V;                             // const div -> IMAD magic
            int q = g4 - p * V;
            float4 v = buf[p * 8 + (q ^ (p & 7))];
            __stcs(&out4[base4 + (size_t)p * DIM_OUT4 + (K0 / 4) + q], v);
        }
    }
    __syncthreads();
}

// -------- tail path: guarded drain (only possible in the last block) --------
template <int K0, int KPP>
__device__ __forceinline__ void pass_tail(const float* xr, const float* yr,
                                          float4* buf, float4* __restrict__ out4,
                                          size_t base4, int tid, int validPairs) {
    compute_and_stage<K0, KPP>(xr, yr, buf, tid);
    __syncthreads();
    constexpr int V = KPP / 4;
    int tot4 = validPairs * V;
    for (int g4 = tid; g4 < tot4; g4 += TPB) {
        int p = g4 / V;
        int q = g4 - p * V;
        float4 v = buf[p * 8 + (q ^ (p & 7))];
        out4[base4 + (size_t)p * DIM_OUT4 + (K0 / 4) + q] = v;
    }
    __syncthreads();
}

__global__ void __launch_bounds__(TPB)
tp_kernel(const float* __restrict__ x, const float* __restrict__ y,
          float* __restrict__ out, int npairs) {
    __shared__ float4 buf[TPB * 8];                     // 16384 B
    const int tid = threadIdx.x;
    const bool full = (blockIdx.x + 1) * TPB <= npairs; // block-uniform

    float xr[7], yr[7];
    float4* out4 = reinterpret_cast<float4*>(out);
    const size_t base4 = (size_t)blockIdx.x * (TPB * DIM_OUT4);

    if (full) {
        // Cooperative vectorized input staging: 224 float4 per array.
        const float4* x4 = reinterpret_cast<const float4*>(x + (size_t)blockIdx.x * TPB * 7);
        const float4* y4 = reinterpret_cast<const float4*>(y + (size_t)blockIdx.x * TPB * 7);
        buf[tid]       = x4[tid];
        buf[224 + tid] = y4[tid];
        if (tid < 96) {
            buf[128 + tid] = x4[128 + tid];
            buf[352 + tid] = y4[128 + tid];
        }
        __syncthreads();
        const float* bf = reinterpret_cast<const float*>(buf);
        #pragma unroll
        for (int i = 0; i < 7; ++i) {                   // 7*tid mod 32: conflict-free
            xr[i] = bf[tid * 7 + i];
            yr[i] = bf[896 + tid * 7 + i];
        }
        __syncthreads();

        pass_fast<0,   32>(xr, yr, buf, out4, base4, tid);
        pass_fast<32,  32>(xr, yr, buf, out4, base4, tid);
        pass_fast<64,  32>(xr, yr, buf, out4, base4, tid);
        pass_fast<96,  32>(xr, yr, buf, out4, base4, tid);
        pass_fast<128, 28>(xr, yr, buf, out4, base4, tid);
    } else {
        int pair = blockIdx.x * TPB + tid;
        if (pair < npairs) {
            const float* xp = x + (size_t)pair * 7;
            const float* yp = y + (size_t)pair * 7;
            #pragma unroll
            for (int i = 0; i < 7; ++i) { xr[i] = __ldg(xp + i); yr[i] = __ldg(yp + i); }
        } else {
            #pragma unroll
            for (int i = 0; i < 7; ++i) { xr[i] = 0.0f; yr[i] = 0.0f; }
        }
        int validPairs = npairs - blockIdx.x * TPB;
        pass_tail<0,   32>(xr, yr, buf, out4, base4, tid, validPairs);
        pass_tail<32,  32>(xr, yr, buf, out4, base4, tid, validPairs);
        pass_tail<64,  32>(xr, yr, buf, out4, base4, tid, validPairs);
        pass_tail<96,  32>(xr, yr, buf, out4, base4, tid, validPairs);
        pass_tail<128, 28>(xr, yr, buf, out4, base4, tid, validPairs);
    }
}

}  // namespace tp

extern "C" void kernel_launch(void* const* d_in, const int* in_sizes, int n_in,
                              void* d_out, int out_size) {
    (void)n_in; (void)out_size;
    const float* x = (const float*)d_in[0];
    const float* y = (const float*)d_in[1];
    float* out = (float*)d_out;
    int npairs = in_sizes[0] / 7;               // E * C
    int blocks = (npairs + tp::TPB - 1) / tp::TPB;
    tp::tp_kernel<<<blocks, tp::TPB>>>(x, y, out, npairs);
}

// round 11
// speedup vs baseline: 1.2589x; 1.0275x over previous
#include <cuda_runtime.h>
#include <utility>
#include <cstddef>

// ============================================================================
// SO(3) tensor product: out[n,c,k] = sum_{i,j} cg[i,j,k] * x[n,c,i] * y[n,c,j]
// CG coefficients are compile-time constants (FFMA immediates).
// R10: fully warp-local pipeline. Each warp owns 32 pairs and a private
// double-buffered smem region; all ordering via __syncwarp (no block barriers
// in the fast path). Drain of pass N overlaps FFMA+stage of pass N+1.
// ============================================================================

namespace tp {

struct CGE { int i; int j; int k; float v; };

__host__ __device__ constexpr double cfact(int n) {
    double r = 1.0;
    for (int i = 2; i <= n; ++i) r *= (double)i;
    return r;
}

__host__ __device__ constexpr double csqrt(double x) {
    if (x <= 0.0) return 0.0;
    double g = x < 1.0 ? 1.0 : x;
    for (int it = 0; it < 48; ++it) g = 0.5 * (g + x / g);
    return g;
}

__host__ __device__ constexpr double w3j(int j1, int j2, int j3,
                                         int m1, int m2, int m3) {
    if (m1 + m2 + m3 != 0) return 0.0;
    int dlo = j1 > j2 ? j1 - j2 : j2 - j1;
    if (j3 < dlo || j3 > j1 + j2) return 0.0;
    int t1 = j2 - m1 - j3;
    int t2 = j1 + m2 - j3;
    int t3 = j1 + j2 - j3;
    int t4 = j1 - m1;
    int t5 = j2 + m2;
    int tmin = 0; if (t1 > tmin) tmin = t1; if (t2 > tmin) tmin = t2;
    int tmax = t3; if (t4 < tmax) tmax = t4; if (t5 < tmax) tmax = t5;
    if (tmin > tmax) return 0.0;
    double s = 0.0;
    for (int t = tmin; t <= tmax; ++t) {
        double term = 1.0 / (cfact(t) * cfact(t - t1) * cfact(t - t2)
                             * cfact(t3 - t) * cfact(t4 - t) * cfact(t5 - t));
        if (t & 1) term = -term;
        s += term;
    }
    double pref = csqrt(
        cfact(j1 + j2 - j3) * cfact(j1 - j2 + j3) * cfact(-j1 + j2 + j3)
        / cfact(j1 + j2 + j3 + 1)
        * cfact(j1 + m1) * cfact(j1 - m1)
        * cfact(j2 + m2) * cfact(j2 - m2)
        * cfact(j3 + m3) * cfact(j3 - m3));
    int ex = j1 - j2 - m3;
    if (ex % 2 != 0) pref = -pref;
    return pref * s;
}

__host__ __device__ constexpr int cg_count_below(int K) {
    int n = 0;
    int off = 0;
    for (int l1 = 0; l1 <= 3; ++l1)
    for (int l2 = 0; l2 <= 3; ++l2) {
        int lo = l1 > l2 ? l1 - l2 : l2 - l1;
        int hi = (l1 + l2) < 3 ? (l1 + l2) : 3;
        for (int l3 = lo; l3 <= hi; ++l3) {
            for (int m3 = -l3; m3 <= l3; ++m3) {
                int k = off + m3 + l3;
                if (k < K) {
                    for (int m1 = -l1; m1 <= l1; ++m1) {
                        int m2 = -m1 - m3;
                        if (m2 < -l2 || m2 > l2) continue;
                        double w = w3j(l1, l2, l3, m1, m2, m3);
                        if (w > 1e-12 || w < -1e-12) ++n;
                    }
                }
            }
            off += 2 * l3 + 1;
        }
    }
    return n;
}

__host__ __device__ constexpr CGE cg_entry(int idx) {
    int n = 0;
    int off = 0;
    for (int l1 = 0; l1 <= 3; ++l1)
    for (int l2 = 0; l2 <= 3; ++l2) {
        int lo = l1 > l2 ? l1 - l2 : l2 - l1;
        int hi = (l1 + l2) < 3 ? (l1 + l2) : 3;
        for (int l3 = lo; l3 <= hi; ++l3) {
            for (int m3 = -l3; m3 <= l3; ++m3) {
                int k = off + m3 + l3;
                for (int m1 = -l1; m1 <= l1; ++m1) {
                    int m2 = -m1 - m3;
                    if (m2 < -l2 || m2 > l2) continue;
                    double w = w3j(l1, l2, l3, m1, m2, m3);
                    if (w > 1e-12 || w < -1e-12) {
                        if (n == idx) return CGE{m1 + l1, m2 + l2, k, (float)w};
                        ++n;
                    }
                }
            }
            off += 2 * l3 + 1;
        }
    }
    return CGE{0, 0, 0, 0.0f};
}

constexpr int DIM_OUT  = 156;
constexpr int DIM_OUT4 = DIM_OUT / 4;   // 39
constexpr int TPB   = 128;
constexpr int WARPS = TPB / 32;

template <int E, int K0>
__device__ __forceinline__ void term(const float* xr, const float* yr, float* acc) {
    constexpr CGE e = cg_entry(E);   // compile-time: immediate coefficient
    acc[e.k - K0] = fmaf(e.v, xr[e.i] * yr[e.j], acc[e.k - K0]);
}

template <int K0, int E0, size_t... Is>
__device__ __forceinline__ void terms(std::index_sequence<Is...>,
                                      const float* xr, const float* yr, float* acc) {
    (term<E0 + (int)Is, K0>(xr, yr, acc), ...);
}

// Compute KPP outputs for this lane's pair and stage into the warp's smem
// region (XOR-swizzled, stride 8 float4 per pair -> conflict-free).
template <int K0, int KPP>
__device__ __forceinline__ void stage(const float* xr, const float* yr,
                                      float4* wbuf, int lane) {
    float acc[KPP] = {};
    constexpr int E0 = cg_count_below(K0);
    constexpr int E1 = cg_count_below(K0 + KPP);
    terms<K0, E0>(std::make_index_sequence<(size_t)(E1 - E0)>{}, xr, yr, acc);
    constexpr int V = KPP / 4;
    #pragma unroll
    for (int q = 0; q < V; ++q)
        wbuf[lane * 8 + (q ^ (lane & 7))] =
            make_float4(acc[4 * q + 0], acc[4 * q + 1], acc[4 * q + 2], acc[4 * q + 3]);
}

// Drain the warp's 32x8 float4 tile: fully static indices, 8 independent
// LDS.128 -> STG.128 chains. wbase4 = first output float4 of this warp's pairs.
template <int K0>
__device__ __forceinline__ void drain32(const float4* wbuf, float4* __restrict__ out4,
                                        size_t wbase4, int lane) {
    const int q = lane & 7;
    const int pl = lane >> 3;
    #pragma unroll
    for (int u = 0; u < 8; ++u) {
        int p = pl + 4 * u;
        float4 v = wbuf[p * 8 + (q ^ (p & 7))];
        __stcs(&out4[wbase4 + (size_t)p * DIM_OUT4 + (K0 / 4) + q], v);
    }
}

// Drain 32x7 float4 (last pass, KPP=28).
template <int K0>
__device__ __forceinline__ void drain28(const float4* wbuf, float4* __restrict__ out4,
                                        size_t wbase4, int lane) {
    #pragma unroll
    for (int u = 0; u < 7; ++u) {
        int g = lane + 32 * u;
        int p = g / 7;                     // const div -> IMAD magic number
        int q = g - p * 7;
        float4 v = wbuf[p * 8 + (q ^ (p & 7))];
        __stcs(&out4[wbase4 + (size_t)p * DIM_OUT4 + (K0 / 4) + q], v);
    }
}

// -------- tail path (only last partial block): guarded, block barriers --------
template <int K0, int KPP>
__device__ __forceinline__ void pass_tail(const float* xr, const float* yr,
                                          float4* buf, float4* __restrict__ out4,
                                          size_t base4, int tid, int validPairs) {
    float acc[KPP] = {};
    constexpr int E0 = cg_count_below(K0);
    constexpr int E1 = cg_count_below(K0 + KPP);
    terms<K0, E0>(std::make_index_sequence<(size_t)(E1 - E0)>{}, xr, yr, acc);
    constexpr int V = KPP / 4;
    #pragma unroll
    for (int q = 0; q < V; ++q)
        buf[tid * 8 + (q ^ (tid & 7))] =
            make_float4(acc[4 * q + 0], acc[4 * q + 1], acc[4 * q + 2], acc[4 * q + 3]);
    __syncthreads();
    int tot4 = validPairs * V;
    for (int g4 = tid; g4 < tot4; g4 += TPB) {
        int p = g4 / V;
        int q = g4 - p * V;
        float4 v = buf[p * 8 + (q ^ (p & 7))];
        out4[base4 + (size_t)p * DIM_OUT4 + (K0 / 4) + q] = v;
    }
    __syncthreads();
}

__global__ void __launch_bounds__(TPB)
tp_kernel(const float* __restrict__ x, const float* __restrict__ y,
          float* __restrict__ out, int npairs) {
    // Per-warp double buffer: [2 buffers][4 warps][32 pairs * 8 float4] = 32 KB.
    __shared__ float4 buf[2 * WARPS * 256];
    const int tid  = threadIdx.x;
    const int lane = tid & 31;
    const int w    = tid >> 5;
    const bool full = (blockIdx.x + 1) * TPB <= npairs;   // block-uniform

    float4* out4 = reinterpret_cast<float4*>(out);

    if (full) {
        float4* wbufA = buf + w * 256;
        float4* wbufB = buf + WARPS * 256 + w * 256;

        const int pair0 = blockIdx.x * TPB + w * 32;      // warp's first pair
        const size_t wbase4 = (size_t)pair0 * DIM_OUT4;

        // Warp-local input staging: 56 float4 of x, 56 of y (896 B each,
        // float4-aligned since pair0 % 32 == 0).
        const float4* x4 = reinterpret_cast<const float4*>(x + (size_t)pair0 * 7);
        const float4* y4 = reinterpret_cast<const float4*>(y + (size_t)pair0 * 7);
        wbufA[lane]      = x4[lane];
        wbufA[56 + lane] = y4[lane];
        if (lane < 24) {
            wbufA[32 + lane] = x4[32 + lane];
            wbufA[88 + lane] = y4[32 + lane];
        }
        __syncwarp();

        float xr[7], yr[7];
        const float* bf = reinterpret_cast<const float*>(wbufA);
        #pragma unroll
        for (int i = 0; i < 7; ++i) {     // 7*lane mod 32 bijective: conflict-free
            xr[i] = bf[lane * 7 + i];
            yr[i] = bf[224 + lane * 7 + i];
        }
        __syncwarp();

        // Software-pipelined passes: drain(N) and compute+stage(N+1) share a
        // syncwarp interval -> LDS/STG latency hidden under FFMAs.
        stage<0, 32>(xr, yr, wbufB, lane);
        __syncwarp();
        stage<32, 32>(xr, yr, wbufA, lane);
        drain32<0>(wbufB, out4, wbase4, lane);
        __syncwarp();
        stage<64, 32>(xr, yr, wbufB, lane);
        drain32<32>(wbufA, out4, wbase4, lane);
        __syncwarp();
        stage<96, 32>(xr, yr, wbufA, lane);
        drain32<64>(wbufB, out4, wbase4, lane);
        __syncwarp();
        stage<128, 28>(xr, yr, wbufB, lane);
        drain32<96>(wbufA, out4, wbase4, lane);
        __syncwarp();
        drain28<128>(wbufB, out4, wbase4, lane);
    } else {
        float xr[7], yr[7];
        int pair = blockIdx.x * TPB + tid;
        if (pair < npairs) {
            const float* xp = x + (size_t)pair * 7;
            const float* yp = y + (size_t)pair * 7;
            #pragma unroll
            for (int i = 0; i < 7; ++i) { xr[i] = __ldg(xp + i); yr[i] = __ldg(yp + i); }
        } else {
            #pragma unroll
            for (int i = 0; i < 7; ++i) { xr[i] = 0.0f; yr[i] = 0.0f; }
        }
        int validPairs = npairs - blockIdx.x * TPB;
        const size_t base4 = (size_t)blockIdx.x * (TPB * DIM_OUT4);
        pass_tail<0,   32>(xr, yr, buf, out4, base4, tid, validPairs);
        pass_tail<32,  32>(xr, yr, buf, out4, base4, tid, validPairs);
        pass_tail<64,  32>(xr, yr, buf, out4, base4, tid, validPairs);
        pass_tail<96,  32>(xr, yr, buf, out4, base4, tid, validPairs);
        pass_tail<128, 28>(xr, yr, buf, out4, base4, tid, validPairs);
    }
}

}  // namespace tp

extern "C" void kernel_launch(void* const* d_in, const int* in_sizes, int n_in,
                              void* d_out, int out_size) {
    (void)n_in; (void)out_size;
    const float* x = (const float*)d_in[0];
    const float* y = (const float*)d_in[1];
    float* out = (float*)d_out;
    int npairs = in_sizes[0] / 7;               // E * C
    int blocks = (npairs + tp::TPB - 1) / tp::TPB;
    tp::tp_kernel<<<blocks, tp::TPB>>>(x, y, out, npairs);
}